// round 9
// baseline (speedup 1.0000x reference)
#include <cuda_runtime.h>
#include <cuda_fp16.h>
#include <mma.h>
#include <math.h>

using namespace nvcuda;

#define NN 100000
#define NE 1600000
#define F  32
#define BN 128                       // nodes per fused block
#define NBLK ((NN + BN - 1) / BN)    // 782

// Scratch (__device__ globals; no allocations allowed).
__device__ float    g_deg_out[NN];
__device__ float    g_deg_in[NN];
__device__ __half2  g_Sout[NN * F / 2];
__device__ __half2  g_Sin [NN * F / 2];
__device__ __half2  g_xh  [NN * F / 2];
__device__ __half   g_Wc[96 * 64];      // stacked weights, cols: z(0:32)|h(32:64)
__device__ float    g_acc;
__device__ unsigned g_ticket;

__device__ __forceinline__ unsigned mulw_h2(unsigned u, float w) {
    __half2 h = *reinterpret_cast<__half2*>(&u);
    float2  f = __half22float2(h);
    __half2 r = __floats2half2_rn(f.x * w, f.y * w);
    return *reinterpret_cast<unsigned*>(&r);
}

__device__ __forceinline__ void red_v4h2(__half2* p, unsigned a, unsigned b,
                                         unsigned c, unsigned d) {
    asm volatile("red.global.add.noftz.v4.f16x2 [%0], {%1,%2,%3,%4};"
                 :: "l"(p), "r"(a), "r"(b), "r"(c), "r"(d) : "memory");
}

__device__ __forceinline__ float fast_tanh(float x) {
    float r;
    asm("tanh.approx.f32 %0, %1;" : "=f"(r) : "f"(x));
    return r;
}

// ---------------- prep: zero scratch, x -> fp16, build combined weight Wc
__global__ void k_prep(const float* __restrict__ x,
                       const float* __restrict__ Wz,
                       const float* __restrict__ Wh) {
    int idx = blockIdx.x * blockDim.x + threadIdx.x;   // covers NN*F/2 = 1.6M
    if (idx < NN * F / 2) {
        g_Sout[idx] = __half2half2(__float2half(0.f));
        g_Sin [idx] = __half2half2(__float2half(0.f));
        float2 v = reinterpret_cast<const float2*>(x)[idx];
        g_xh[idx] = __floats2half2_rn(v.x, v.y);
    }
    if (idx < NN) { g_deg_out[idx] = 0.f; g_deg_in[idx] = 0.f; }
    if (idx < 96 * 64) {
        int i = idx >> 6, j = idx & 63;
        int jj = j & 31;
        const float* W = (j < 32) ? Wz : Wh;
        float v;
        if (i < 32)      v = W[i * 32 + jj] + W[(128 + i) * 32 + jj]; // A = W[0,0]+W[1,0]
        else if (i < 64) v = W[(32 + i) * 32 + jj];                   // B = W[0,1]
        else             v = W[(128 + i) * 32 + jj];                  // C = W[1,1]
        g_Wc[idx] = __float2half(v);
    }
    if (idx == 0) { g_acc = 0.f; g_ticket = 0u; }
}

// --------------------------------- no-op spacer (profiler window alignment)
__global__ void k_nop() {}

// ------------------------------------------------- edge scatter (+ degrees)
// At the L2-throughput roofline for this access pattern (~410 MB random RMW).
__global__ void k_scatter(const float* __restrict__ ew,
                          const int*   __restrict__ ei) {
    int t = blockIdx.x * blockDim.x + threadIdx.x;
    int p = t >> 2;
    int c = t & 3;
    int e0 = 2 * p, e1 = 2 * p + 1;

    int   src0 = __ldg(&ei[e0]),      src1 = __ldg(&ei[e1]);
    int   dst0 = __ldg(&ei[NE + e0]), dst1 = __ldg(&ei[NE + e1]);
    float w0   = __ldg(&ew[e0]),      w1   = __ldg(&ew[e1]);

    const uint4* xh4 = reinterpret_cast<const uint4*>(g_xh);
    uint4 xd0 = xh4[dst0 * 4 + c];
    uint4 xs0 = xh4[src0 * 4 + c];
    uint4 xd1 = xh4[dst1 * 4 + c];
    uint4 xs1 = xh4[src1 * 4 + c];

    red_v4h2(&g_Sout[src0 * (F / 2) + c * 4],
             mulw_h2(xd0.x, w0), mulw_h2(xd0.y, w0),
             mulw_h2(xd0.z, w0), mulw_h2(xd0.w, w0));
    red_v4h2(&g_Sin[dst0 * (F / 2) + c * 4],
             mulw_h2(xs0.x, w0), mulw_h2(xs0.y, w0),
             mulw_h2(xs0.z, w0), mulw_h2(xs0.w, w0));
    red_v4h2(&g_Sout[src1 * (F / 2) + c * 4],
             mulw_h2(xd1.x, w1), mulw_h2(xd1.y, w1),
             mulw_h2(xd1.z, w1), mulw_h2(xd1.w, w1));
    red_v4h2(&g_Sin[dst1 * (F / 2) + c * 4],
             mulw_h2(xs1.x, w1), mulw_h2(xs1.y, w1),
             mulw_h2(xs1.z, w1), mulw_h2(xs1.w, w1));

    if (c == 0) {
        asm volatile("red.global.add.f32 [%0], %1;" :: "l"(&g_deg_out[src0]), "f"(w0) : "memory");
        asm volatile("red.global.add.f32 [%0], %1;" :: "l"(&g_deg_in[dst0]),  "f"(w0) : "memory");
        asm volatile("red.global.add.f32 [%0], %1;" :: "l"(&g_deg_out[src1]), "f"(w1) : "memory");
        asm volatile("red.global.add.f32 [%0], %1;" :: "l"(&g_deg_in[dst1]),  "f"(w1) : "memory");
    }
}

// ---- fused: block-cooperative A staging + wmma + gates + global reduce
// 128 nodes per block, 8 warps. Two-pass epilogue reuses each warp's dead
// A slice as its C buffer (per-warp private -> only __syncwarp needed).
__global__ void __launch_bounds__(256, 5) k_fused(
        const float* __restrict__ bz, const float* __restrict__ bh,
        const float* __restrict__ wlin, const float* __restrict__ blin,
        float* __restrict__ out) {
    __shared__ __half sW[96 * 64];                   // 12 KB
    __shared__ __align__(16) char buf[24576];        // A panel [128 x 96] fp16
    __shared__ float sB[64];
    __shared__ float sL[32];
    __shared__ float wsum[8];

    int tid = threadIdx.x;   // 256 = 8 warps
    int n0 = blockIdx.x * BN;

    for (int i = tid; i < (96 * 64) / 2; i += 256)
        reinterpret_cast<__half2*>(sW)[i] = reinterpret_cast<const __half2*>(g_Wc)[i];
    if (tid < 32) { sB[tid] = bz[tid]; sB[32 + tid] = bh[tid]; sL[tid] = wlin[tid]; }

    // Stage A panel: rows = nodes, 48 half2/row = [x(16) | P(16) | Q(16)].
    // Sources are three contiguous 2048-half2 spans -> fully coalesced.
    {
        __half2* sA2 = reinterpret_cast<__half2*>(buf);
        const __half2 hz = __half2half2(__float2half(0.f));
        int lim = (NN - n0) * 16;                    // valid half2 in this block
        #pragma unroll
        for (int it = 0; it < 8; it++) {
            int idx  = it * 256 + tid;               // 0..2047
            int node = idx >> 4, c = idx & 15;
            __half2 vx = hz, vp = hz, vq = hz;
            if (idx < lim) {
                int n = n0 + node;
                vx = g_xh[n0 * 16 + idx];
                float invO = 1.f / g_deg_out[n];
                float invI = 1.f / g_deg_in[n];
                float2 fo = __half22float2(g_Sout[n0 * 16 + idx]);
                vp = __floats2half2_rn(fo.x * invO, fo.y * invO);
                float2 fi = __half22float2(g_Sin[n0 * 16 + idx]);
                vq = __floats2half2_rn(fi.x * invI, fi.y * invI);
            }
            sA2[node * 48 + c]      = vx;
            sA2[node * 48 + 16 + c] = vp;
            sA2[node * 48 + 32 + c] = vq;
        }
    }
    __syncthreads();

    int warp = tid >> 5, lane = tid & 31;

    // Each warp: 16-node slice of the panel, [16x96]@[96x64]
    const __half* sA = reinterpret_cast<const __half*>(buf) + warp * 16 * 96;
    wmma::fragment<wmma::accumulator, 16, 16, 16, float> c[4];
    #pragma unroll
    for (int nt = 0; nt < 4; nt++) wmma::fill_fragment(c[nt], 0.f);
    #pragma unroll
    for (int kt = 0; kt < 6; kt++) {
        wmma::fragment<wmma::matrix_a, 16, 16, 16, __half, wmma::row_major> a;
        wmma::load_matrix_sync(a, sA + kt * 16, 96);
        #pragma unroll
        for (int nt = 0; nt < 4; nt++) {
            wmma::fragment<wmma::matrix_b, 16, 16, 16, __half, wmma::row_major> b;
            wmma::load_matrix_sync(b, sW + kt * 16 * 64 + nt * 16, 64);
            wmma::mma_sync(c[nt], a, b, c[nt]);
        }
    }
    __syncwarp();   // A slice (private to this warp) now dead; reuse as C buf

    float* sC = reinterpret_cast<float*>(
        const_cast<__half*>(sA));                    // 3 KB, holds 2 KB per pass
    float sum = 0.f;
    int nwarp0 = n0 + warp * 16;
    #pragma unroll
    for (int p = 0; p < 2; p++) {
        // z cols p*16..p*16+15 (tile p), h cols 32+p*16.. (tile 2+p)
        wmma::store_matrix_sync(sC,       c[p],     16, wmma::mem_row_major);
        wmma::store_matrix_sync(sC + 256, c[2 + p], 16, wmma::mem_row_major);
        __syncwarp();
        #pragma unroll
        for (int it = lane; it < 256; it += 32) {    // 16 nodes x 16 cols
            int node = it >> 4, jj = it & 15;
            if (nwarp0 + node < NN) {
                int j = p * 16 + jj;
                float zp = sC[it]       + sB[j];
                float hp = sC[256 + it] + sB[32 + j];
                float z  = 1.f / (1.f + __expf(-zp));
                float ht = fast_tanh(hp);
                float H  = (1.f - z) * ht;
                sum += fmaxf(H, 0.f) * sL[j];
            }
        }
        __syncwarp();
    }

    #pragma unroll
    for (int o = 16; o; o >>= 1)
        sum += __shfl_xor_sync(0xffffffffu, sum, o);
    if (lane == 0) wsum[warp] = sum;
    __syncthreads();

    if (tid == 0) {
        float s = 0.f;
        #pragma unroll
        for (int w = 0; w < 8; w++) s += wsum[w];
        atomicAdd(&g_acc, s);
        __threadfence();
        unsigned done = atomicAdd(&g_ticket, 1u);
        if (done == NBLK - 1) {
            float total = atomicAdd(&g_acc, 0.f);   // coherent read
            out[0] = total / (float)NN + blin[0];
        }
    }
}

extern "C" void kernel_launch(void* const* d_in, const int* in_sizes, int n_in,
                              void* d_out, int out_size) {
    const float* x    = (const float*)d_in[0];
    const float* ew   = (const float*)d_in[1];
    const float* Wz   = (const float*)d_in[2];
    const float* bz   = (const float*)d_in[3];
    // d_in[4] = W_r, d_in[5] = b_r : dead (H=0 => H*R=0)
    const float* Wh   = (const float*)d_in[6];
    const float* bh   = (const float*)d_in[7];
    const float* wlin = (const float*)d_in[8];
    const float* blin = (const float*)d_in[9];
    const int*   ei   = (const int*)d_in[10];

    k_prep   <<<(NN * F / 2 + 255) / 256, 256>>>(x, Wz, Wh);    // 1
    k_scatter<<<(NE * 2) / 256, 256>>>(ew, ei);                 // 2
    k_nop    <<<1, 32>>>();                                     // 3
    k_fused  <<<NBLK, 256>>>(bz, bh, wlin, blin, (float*)d_out);// 4 <- profiled
}

// round 10
// speedup vs baseline: 1.0445x; 1.0445x over previous
#include <cuda_runtime.h>
#include <cuda_fp16.h>
#include <mma.h>
#include <math.h>

using namespace nvcuda;

#define NN 100000
#define NE 1600000
#define F  32
#define BN 128                       // nodes per fused block
#define NBLK ((NN + BN - 1) / BN)    // 782

// Scratch (__device__ globals; no allocations allowed).
__device__ float    g_deg_out[NN];
__device__ float    g_deg_in[NN];
__device__ __half2  g_Sout[NN * F / 2];
__device__ __half2  g_Sin [NN * F / 2];
__device__ __half2  g_xh  [NN * F / 2];
__device__ __half   g_Wc[96 * 64];      // stacked weights, cols: z(0:32)|h(32:64)
__device__ float    g_acc;
__device__ unsigned g_ticket;

__device__ __forceinline__ unsigned mulw_h2(unsigned u, float w) {
    __half2 h = *reinterpret_cast<__half2*>(&u);
    float2  f = __half22float2(h);
    __half2 r = __floats2half2_rn(f.x * w, f.y * w);
    return *reinterpret_cast<unsigned*>(&r);
}

__device__ __forceinline__ void red_v4h2(__half2* p, unsigned a, unsigned b,
                                         unsigned c, unsigned d) {
    asm volatile("red.global.add.noftz.v4.f16x2 [%0], {%1,%2,%3,%4};"
                 :: "l"(p), "r"(a), "r"(b), "r"(c), "r"(d) : "memory");
}

// ---------------- prep: zero scratch, x -> fp16, build combined weight Wc
__global__ void k_prep(const float* __restrict__ x,
                       const float* __restrict__ Wz,
                       const float* __restrict__ Wh) {
    int idx = blockIdx.x * blockDim.x + threadIdx.x;   // covers NN*F/2 = 1.6M
    if (idx < NN * F / 2) {
        g_Sout[idx] = __half2half2(__float2half(0.f));
        g_Sin [idx] = __half2half2(__float2half(0.f));
        float2 v = reinterpret_cast<const float2*>(x)[idx];
        g_xh[idx] = __floats2half2_rn(v.x, v.y);
    }
    if (idx < NN) { g_deg_out[idx] = 0.f; g_deg_in[idx] = 0.f; }
    if (idx < 96 * 64) {
        int i = idx >> 6, j = idx & 63;
        int jj = j & 31;
        const float* W = (j < 32) ? Wz : Wh;
        float v;
        if (i < 32)      v = W[i * 32 + jj] + W[(128 + i) * 32 + jj]; // A = W[0,0]+W[1,0]
        else if (i < 64) v = W[(32 + i) * 32 + jj];                   // B = W[0,1]
        else             v = W[(128 + i) * 32 + jj];                  // C = W[1,1]
        g_Wc[idx] = __float2half(v);
    }
    if (idx == 0) { g_acc = 0.f; g_ticket = 0u; }
}

// --------------------------------- no-op spacer (profiler window alignment)
__global__ void k_nop() {}

// ------------------------------------------------- edge scatter (+ degrees)
// At the L2-throughput roofline for this access pattern (~410 MB random RMW).
__global__ void k_scatter(const float* __restrict__ ew,
                          const int*   __restrict__ ei) {
    int t = blockIdx.x * blockDim.x + threadIdx.x;
    int p = t >> 2;
    int c = t & 3;
    int e0 = 2 * p, e1 = 2 * p + 1;

    int   src0 = __ldg(&ei[e0]),      src1 = __ldg(&ei[e1]);
    int   dst0 = __ldg(&ei[NE + e0]), dst1 = __ldg(&ei[NE + e1]);
    float w0   = __ldg(&ew[e0]),      w1   = __ldg(&ew[e1]);

    const uint4* xh4 = reinterpret_cast<const uint4*>(g_xh);
    uint4 xd0 = xh4[dst0 * 4 + c];
    uint4 xs0 = xh4[src0 * 4 + c];
    uint4 xd1 = xh4[dst1 * 4 + c];
    uint4 xs1 = xh4[src1 * 4 + c];

    red_v4h2(&g_Sout[src0 * (F / 2) + c * 4],
             mulw_h2(xd0.x, w0), mulw_h2(xd0.y, w0),
             mulw_h2(xd0.z, w0), mulw_h2(xd0.w, w0));
    red_v4h2(&g_Sin[dst0 * (F / 2) + c * 4],
             mulw_h2(xs0.x, w0), mulw_h2(xs0.y, w0),
             mulw_h2(xs0.z, w0), mulw_h2(xs0.w, w0));
    red_v4h2(&g_Sout[src1 * (F / 2) + c * 4],
             mulw_h2(xd1.x, w1), mulw_h2(xd1.y, w1),
             mulw_h2(xd1.z, w1), mulw_h2(xd1.w, w1));
    red_v4h2(&g_Sin[dst1 * (F / 2) + c * 4],
             mulw_h2(xs1.x, w1), mulw_h2(xs1.y, w1),
             mulw_h2(xs1.z, w1), mulw_h2(xs1.w, w1));

    if (c == 0) {
        asm volatile("red.global.add.f32 [%0], %1;" :: "l"(&g_deg_out[src0]), "f"(w0) : "memory");
        asm volatile("red.global.add.f32 [%0], %1;" :: "l"(&g_deg_in[dst0]),  "f"(w0) : "memory");
        asm volatile("red.global.add.f32 [%0], %1;" :: "l"(&g_deg_out[src1]), "f"(w1) : "memory");
        asm volatile("red.global.add.f32 [%0], %1;" :: "l"(&g_deg_in[dst1]),  "f"(w1) : "memory");
    }
}

// ---- fused: block-cooperative A staging + wmma + gates + global reduce
// 128 nodes per block, 8 warps. Epilogue: one tanh.approx.f16x2 per item
// via sigmoid(x) = (1+tanh(x/2))/2  =>  H = 0.5*(1-tanh(zp/2))*tanh(hp).
__global__ void __launch_bounds__(256, 5) k_fused(
        const float* __restrict__ bz, const float* __restrict__ bh,
        const float* __restrict__ wlin, const float* __restrict__ blin,
        float* __restrict__ out) {
    __shared__ __half sW[96 * 64];                   // 12 KB
    __shared__ __align__(16) char buf[24576];        // A panel [128 x 96] fp16
    __shared__ float sDegO[BN], sDegI[BN];
    __shared__ float sB[64];
    __shared__ float sL[32];
    __shared__ float wsum[8];

    int tid = threadIdx.x;   // 256 = 8 warps
    int n0 = blockIdx.x * BN;

    for (int i = tid; i < (96 * 64) / 2; i += 256)
        reinterpret_cast<__half2*>(sW)[i] = reinterpret_cast<const __half2*>(g_Wc)[i];
    if (tid < 32) { sB[tid] = bz[tid]; sB[32 + tid] = bh[tid]; sL[tid] = wlin[tid]; }
    if (tid < BN) {
        int n = n0 + tid;
        sDegO[tid] = (n < NN) ? 1.f / g_deg_out[n] : 0.f;
        sDegI[tid] = (n < NN) ? 1.f / g_deg_in[n]  : 0.f;
    }
    __syncthreads();

    // Stage A panel: rows = nodes, 48 half2/row = [x(16) | P(16) | Q(16)].
    // Sources are three contiguous 2048-half2 spans -> fully coalesced.
    {
        __half2* sA2 = reinterpret_cast<__half2*>(buf);
        const __half2 hz = __half2half2(__float2half(0.f));
        int lim = (NN - n0) * 16;                    // valid half2 in this block
        #pragma unroll
        for (int it = 0; it < 8; it++) {
            int idx  = it * 256 + tid;               // 0..2047
            int node = idx >> 4, c = idx & 15;
            __half2 vx = hz, vp = hz, vq = hz;
            if (idx < lim) {
                vx = g_xh[n0 * 16 + idx];
                float invO = sDegO[node], invI = sDegI[node];
                float2 fo = __half22float2(g_Sout[n0 * 16 + idx]);
                vp = __floats2half2_rn(fo.x * invO, fo.y * invO);
                float2 fi = __half22float2(g_Sin[n0 * 16 + idx]);
                vq = __floats2half2_rn(fi.x * invI, fi.y * invI);
            }
            sA2[node * 48 + c]      = vx;
            sA2[node * 48 + 16 + c] = vp;
            sA2[node * 48 + 32 + c] = vq;
        }
    }
    __syncthreads();

    int warp = tid >> 5, lane = tid & 31;

    // Each warp: 16-node slice of the panel, [16x96]@[96x64]
    const __half* sA = reinterpret_cast<const __half*>(buf) + warp * 16 * 96;
    wmma::fragment<wmma::accumulator, 16, 16, 16, float> c[4];
    #pragma unroll
    for (int nt = 0; nt < 4; nt++) wmma::fill_fragment(c[nt], 0.f);
    #pragma unroll
    for (int kt = 0; kt < 6; kt++) {
        wmma::fragment<wmma::matrix_a, 16, 16, 16, __half, wmma::row_major> a;
        wmma::load_matrix_sync(a, sA + kt * 16, 96);
        #pragma unroll
        for (int nt = 0; nt < 4; nt++) {
            wmma::fragment<wmma::matrix_b, 16, 16, 16, __half, wmma::row_major> b;
            wmma::load_matrix_sync(b, sW + kt * 16 * 64 + nt * 16, 64);
            wmma::mma_sync(c[nt], a, b, c[nt]);
        }
    }
    __syncwarp();   // A slice (private to this warp) now dead; reuse as C buf

    float* sC = reinterpret_cast<float*>(
        const_cast<__half*>(sA));                    // 3 KB, holds 2 KB per pass
    float sum = 0.f;
    int nwarp0 = n0 + warp * 16;
    #pragma unroll
    for (int p = 0; p < 2; p++) {
        // z cols p*16..p*16+15 (tile p), h cols 32+p*16.. (tile 2+p)
        wmma::store_matrix_sync(sC,       c[p],     16, wmma::mem_row_major);
        wmma::store_matrix_sync(sC + 256, c[2 + p], 16, wmma::mem_row_major);
        __syncwarp();
        #pragma unroll
        for (int it = lane; it < 256; it += 32) {    // 16 nodes x 16 cols
            int node = it >> 4, jj = it & 15;
            if (nwarp0 + node < NN) {
                int j = p * 16 + jj;
                float zp = sC[it]       + sB[j];
                float hp = sC[256 + it] + sB[32 + j];
                // one MUFU: tanh.approx.f16x2 of (zp/2, hp)
                __half2 arg = __floats2half2_rn(0.5f * zp, hp);
                unsigned ua = *reinterpret_cast<unsigned*>(&arg);
                unsigned ut;
                asm("tanh.approx.f16x2 %0, %1;" : "=r"(ut) : "r"(ua));
                __half2 th = *reinterpret_cast<__half2*>(&ut);
                float2 tf = __half22float2(th);
                float H = 0.5f * (1.f - tf.x) * tf.y;
                sum += fmaxf(H, 0.f) * sL[j];
            }
        }
        __syncwarp();
    }

    #pragma unroll
    for (int o = 16; o; o >>= 1)
        sum += __shfl_xor_sync(0xffffffffu, sum, o);
    if (lane == 0) wsum[warp] = sum;
    __syncthreads();

    if (tid == 0) {
        float s = 0.f;
        #pragma unroll
        for (int w = 0; w < 8; w++) s += wsum[w];
        atomicAdd(&g_acc, s);
        __threadfence();
        unsigned done = atomicAdd(&g_ticket, 1u);
        if (done == NBLK - 1) {
            float total = atomicAdd(&g_acc, 0.f);   // coherent read
            out[0] = total / (float)NN + blin[0];
        }
    }
}

extern "C" void kernel_launch(void* const* d_in, const int* in_sizes, int n_in,
                              void* d_out, int out_size) {
    const float* x    = (const float*)d_in[0];
    const float* ew   = (const float*)d_in[1];
    const float* Wz   = (const float*)d_in[2];
    const float* bz   = (const float*)d_in[3];
    // d_in[4] = W_r, d_in[5] = b_r : dead (H=0 => H*R=0)
    const float* Wh   = (const float*)d_in[6];
    const float* bh   = (const float*)d_in[7];
    const float* wlin = (const float*)d_in[8];
    const float* blin = (const float*)d_in[9];
    const int*   ei   = (const int*)d_in[10];

    k_prep   <<<(NN * F / 2 + 255) / 256, 256>>>(x, Wz, Wh);    // 1
    k_scatter<<<(NE * 2) / 256, 256>>>(ew, ei);                 // 2
    k_nop    <<<1, 32>>>();                                     // 3
    k_fused  <<<NBLK, 256>>>(bz, bh, wlin, blin, (float*)d_out);// 4 <- profiled
}

// round 11
// speedup vs baseline: 1.2804x; 1.2259x over previous
#include <cuda_runtime.h>
#include <cuda_fp16.h>
#include <mma.h>
#include <math.h>

using namespace nvcuda;

#define NN 100000
#define NE 1600000
#define F  32
#define BN 128                       // nodes per fused block
#define NBLK ((NN + BN - 1) / BN)    // 782
#define LDA 104                      // A panel ldm (halves): 208B stride, conflict-free LDSM
#define LDW 72                       // W ldm (halves): 144B stride, conflict-free LDSM
#define LDC 20                       // C ldm (floats): 80B stride, conflict-free

// Scratch (__device__ globals; no allocations allowed).
__device__ float    g_deg_out[NN];
__device__ float    g_deg_in[NN];
__device__ __half2  g_Sout[NN * F / 2];
__device__ __half2  g_Sin [NN * F / 2];
__device__ __half2  g_xh  [NN * F / 2];
__device__ __half   g_Wc[96 * 64];      // stacked weights, cols: z(0:32)|h(32:64)
__device__ float    g_acc;
__device__ unsigned g_ticket;

__device__ __forceinline__ unsigned mulw_h2(unsigned u, float w) {
    __half2 h = *reinterpret_cast<__half2*>(&u);
    float2  f = __half22float2(h);
    __half2 r = __floats2half2_rn(f.x * w, f.y * w);
    return *reinterpret_cast<unsigned*>(&r);
}

__device__ __forceinline__ void red_v4h2(__half2* p, unsigned a, unsigned b,
                                         unsigned c, unsigned d) {
    asm volatile("red.global.add.noftz.v4.f16x2 [%0], {%1,%2,%3,%4};"
                 :: "l"(p), "r"(a), "r"(b), "r"(c), "r"(d) : "memory");
}

__device__ __forceinline__ float fast_tanh(float x) {
    float r;
    asm("tanh.approx.f32 %0, %1;" : "=f"(r) : "f"(x));
    return r;
}

// ---------------- prep: zero scratch, x -> fp16, build combined weight Wc
__global__ void k_prep(const float* __restrict__ x,
                       const float* __restrict__ Wz,
                       const float* __restrict__ Wh) {
    int idx = blockIdx.x * blockDim.x + threadIdx.x;   // covers NN*F/2 = 1.6M
    if (idx < NN * F / 2) {
        g_Sout[idx] = __half2half2(__float2half(0.f));
        g_Sin [idx] = __half2half2(__float2half(0.f));
        float2 v = reinterpret_cast<const float2*>(x)[idx];
        g_xh[idx] = __floats2half2_rn(v.x, v.y);
    }
    if (idx < NN) { g_deg_out[idx] = 0.f; g_deg_in[idx] = 0.f; }
    if (idx < 96 * 64) {
        int i = idx >> 6, j = idx & 63;
        int jj = j & 31;
        const float* W = (j < 32) ? Wz : Wh;
        float v;
        if (i < 32)      v = W[i * 32 + jj] + W[(128 + i) * 32 + jj]; // A = W[0,0]+W[1,0]
        else if (i < 64) v = W[(32 + i) * 32 + jj];                   // B = W[0,1]
        else             v = W[(128 + i) * 32 + jj];                  // C = W[1,1]
        g_Wc[idx] = __float2half(v);
    }
    if (idx == 0) { g_acc = 0.f; g_ticket = 0u; }
}

// --------------------------------- no-op spacer (profiler window alignment)
__global__ void k_nop() {}

// ------------------------------------------------- edge scatter (+ degrees)
// At the L2-throughput roofline for this access pattern (~410 MB random RMW).
__global__ void k_scatter(const float* __restrict__ ew,
                          const int*   __restrict__ ei) {
    int t = blockIdx.x * blockDim.x + threadIdx.x;
    int p = t >> 2;
    int c = t & 3;
    int e0 = 2 * p, e1 = 2 * p + 1;

    int   src0 = __ldg(&ei[e0]),      src1 = __ldg(&ei[e1]);
    int   dst0 = __ldg(&ei[NE + e0]), dst1 = __ldg(&ei[NE + e1]);
    float w0   = __ldg(&ew[e0]),      w1   = __ldg(&ew[e1]);

    const uint4* xh4 = reinterpret_cast<const uint4*>(g_xh);
    uint4 xd0 = xh4[dst0 * 4 + c];
    uint4 xs0 = xh4[src0 * 4 + c];
    uint4 xd1 = xh4[dst1 * 4 + c];
    uint4 xs1 = xh4[src1 * 4 + c];

    red_v4h2(&g_Sout[src0 * (F / 2) + c * 4],
             mulw_h2(xd0.x, w0), mulw_h2(xd0.y, w0),
             mulw_h2(xd0.z, w0), mulw_h2(xd0.w, w0));
    red_v4h2(&g_Sin[dst0 * (F / 2) + c * 4],
             mulw_h2(xs0.x, w0), mulw_h2(xs0.y, w0),
             mulw_h2(xs0.z, w0), mulw_h2(xs0.w, w0));
    red_v4h2(&g_Sout[src1 * (F / 2) + c * 4],
             mulw_h2(xd1.x, w1), mulw_h2(xd1.y, w1),
             mulw_h2(xd1.z, w1), mulw_h2(xd1.w, w1));
    red_v4h2(&g_Sin[dst1 * (F / 2) + c * 4],
             mulw_h2(xs1.x, w1), mulw_h2(xs1.y, w1),
             mulw_h2(xs1.z, w1), mulw_h2(xs1.w, w1));

    if (c == 0) {
        asm volatile("red.global.add.f32 [%0], %1;" :: "l"(&g_deg_out[src0]), "f"(w0) : "memory");
        asm volatile("red.global.add.f32 [%0], %1;" :: "l"(&g_deg_in[dst0]),  "f"(w0) : "memory");
        asm volatile("red.global.add.f32 [%0], %1;" :: "l"(&g_deg_out[src1]), "f"(w1) : "memory");
        asm volatile("red.global.add.f32 [%0], %1;" :: "l"(&g_deg_in[dst1]),  "f"(w1) : "memory");
    }
}

// ---- fused: block-cooperative A staging + wmma + gates + global reduce
// 128 nodes per block, 8 warps. All smem matrices padded to conflict-free
// strides (LDA=104, LDW=72, LDC=20).
__global__ void __launch_bounds__(256, 5) k_fused(
        const float* __restrict__ bz, const float* __restrict__ bh,
        const float* __restrict__ wlin, const float* __restrict__ blin,
        float* __restrict__ out) {
    __shared__ __half sW[96 * LDW];                  // 13.5 KB
    __shared__ __align__(16) __half sA[BN * LDA];    // 26 KB; per-warp slice reused as C
    __shared__ float sDegO[BN], sDegI[BN];
    __shared__ float sB[64];
    __shared__ float sL[32];
    __shared__ float wsum[8];

    int tid = threadIdx.x;   // 256 = 8 warps
    int n0 = blockIdx.x * BN;

    for (int i = tid; i < 96 * 64; i += 256) {
        int r = i >> 6, cc = i & 63;
        sW[r * LDW + cc] = g_Wc[i];
    }
    if (tid < 32) { sB[tid] = bz[tid]; sB[32 + tid] = bh[tid]; sL[tid] = wlin[tid]; }
    if (tid < BN) {
        int n = n0 + tid;
        sDegO[tid] = (n < NN) ? 1.f / g_deg_out[n] : 0.f;
        sDegI[tid] = (n < NN) ? 1.f / g_deg_in[n]  : 0.f;
    }
    __syncthreads();

    // Stage A panel: rows = nodes, cols (half2): [x(16) | P(16) | Q(16)] of 52.
    // Sources are three contiguous 2048-half2 spans -> fully coalesced loads.
    {
        __half2* sA2 = reinterpret_cast<__half2*>(sA);
        const __half2 hz = __half2half2(__float2half(0.f));
        int lim = (NN - n0) * 16;                    // valid half2 in this block
        #pragma unroll
        for (int it = 0; it < 8; it++) {
            int idx  = it * 256 + tid;               // 0..2047
            int node = idx >> 4, c = idx & 15;
            __half2 vx = hz, vp = hz, vq = hz;
            if (idx < lim) {
                vx = g_xh[n0 * 16 + idx];
                float invO = sDegO[node], invI = sDegI[node];
                float2 fo = __half22float2(g_Sout[n0 * 16 + idx]);
                vp = __floats2half2_rn(fo.x * invO, fo.y * invO);
                float2 fi = __half22float2(g_Sin[n0 * 16 + idx]);
                vq = __floats2half2_rn(fi.x * invI, fi.y * invI);
            }
            sA2[node * (LDA / 2) + c]      = vx;
            sA2[node * (LDA / 2) + 16 + c] = vp;
            sA2[node * (LDA / 2) + 32 + c] = vq;
        }
    }
    __syncthreads();

    int warp = tid >> 5, lane = tid & 31;

    // Each warp: 16-node slice of the panel, [16x96]@[96x64]
    const __half* sAw = sA + warp * 16 * LDA;
    wmma::fragment<wmma::accumulator, 16, 16, 16, float> c[4];
    #pragma unroll
    for (int nt = 0; nt < 4; nt++) wmma::fill_fragment(c[nt], 0.f);
    #pragma unroll
    for (int kt = 0; kt < 6; kt++) {
        wmma::fragment<wmma::matrix_a, 16, 16, 16, __half, wmma::row_major> a;
        wmma::load_matrix_sync(a, sAw + kt * 16, LDA);
        #pragma unroll
        for (int nt = 0; nt < 4; nt++) {
            wmma::fragment<wmma::matrix_b, 16, 16, 16, __half, wmma::row_major> b;
            wmma::load_matrix_sync(b, sW + kt * 16 * LDW + nt * 16, LDW);
            wmma::mma_sync(c[nt], a, b, c[nt]);
        }
    }
    __syncwarp();   // A slice (private to this warp) now dead; reuse as C buf

    float* sC = reinterpret_cast<float*>(const_cast<__half*>(sAw));
    float sum = 0.f;
    int nwarp0 = n0 + warp * 16;
    #pragma unroll
    for (int p = 0; p < 2; p++) {
        // z cols p*16.. (tile p), h cols 32+p*16.. (tile 2+p); 16x20 f32 each
        wmma::store_matrix_sync(sC,            c[p],     LDC, wmma::mem_row_major);
        wmma::store_matrix_sync(sC + 16 * LDC, c[2 + p], LDC, wmma::mem_row_major);
        __syncwarp();
        #pragma unroll
        for (int it = lane; it < 256; it += 32) {    // 16 nodes x 16 cols
            int node = it >> 4, jj = it & 15;
            if (nwarp0 + node < NN) {
                int j = p * 16 + jj;
                float zp = sC[node * LDC + jj]            + sB[j];
                float hp = sC[16 * LDC + node * LDC + jj] + sB[32 + j];
                float z  = 1.f / (1.f + __expf(-zp));
                float ht = fast_tanh(hp);
                float H  = (1.f - z) * ht;
                sum += fmaxf(H, 0.f) * sL[j];
            }
        }
        __syncwarp();
    }

    #pragma unroll
    for (int o = 16; o; o >>= 1)
        sum += __shfl_xor_sync(0xffffffffu, sum, o);
    if (lane == 0) wsum[warp] = sum;
    __syncthreads();

    if (tid == 0) {
        float s = 0.f;
        #pragma unroll
        for (int w = 0; w < 8; w++) s += wsum[w];
        atomicAdd(&g_acc, s);
        __threadfence();
        unsigned done = atomicAdd(&g_ticket, 1u);
        if (done == NBLK - 1) {
            float total = atomicAdd(&g_acc, 0.f);   // coherent read
            out[0] = total / (float)NN + blin[0];
        }
    }
}

extern "C" void kernel_launch(void* const* d_in, const int* in_sizes, int n_in,
                              void* d_out, int out_size) {
    const float* x    = (const float*)d_in[0];
    const float* ew   = (const float*)d_in[1];
    const float* Wz   = (const float*)d_in[2];
    const float* bz   = (const float*)d_in[3];
    // d_in[4] = W_r, d_in[5] = b_r : dead (H=0 => H*R=0)
    const float* Wh   = (const float*)d_in[6];
    const float* bh   = (const float*)d_in[7];
    const float* wlin = (const float*)d_in[8];
    const float* blin = (const float*)d_in[9];
    const int*   ei   = (const int*)d_in[10];

    k_prep   <<<(NN * F / 2 + 255) / 256, 256>>>(x, Wz, Wh);    // 1
    k_scatter<<<(NE * 2) / 256, 256>>>(ew, ei);                 // 2
    k_nop    <<<1, 32>>>();                                     // 3
    k_fused  <<<NBLK, 256>>>(bz, bh, wlin, blin, (float*)d_out);// 4 <- profiled
}

// round 12
// speedup vs baseline: 1.2809x; 1.0004x over previous
#include <cuda_runtime.h>
#include <cuda_fp16.h>
#include <mma.h>
#include <math.h>

using namespace nvcuda;

#define NN 100000
#define NE 1600000
#define F  32
#define BN 128                       // nodes per fused block
#define NBLK ((NN + BN - 1) / BN)    // 782
#define LDA 104                      // A panel ldm (halves): 208B stride, conflict-free LDSM
#define LDW 72                       // W ldm (halves): 144B stride, conflict-free LDSM
#define LDC 20                       // C ldm (floats): 80B stride, conflict-free

// Scratch (__device__ globals; no allocations allowed).
__device__ float    g_deg_out[NN];
__device__ float    g_deg_in[NN];
__device__ __half2  g_Sout[NN * F / 2];
__device__ __half2  g_Sin [NN * F / 2];
__device__ __half2  g_xh  [NN * F / 2];
__device__ __half   g_Wc[96 * 64];      // stacked weights, cols: z(0:32)|h(32:64)
__device__ float    g_acc;
__device__ unsigned g_ticket;

__device__ __forceinline__ unsigned mulw_h2(unsigned u, float w) {
    __half2 h = *reinterpret_cast<__half2*>(&u);
    float2  f = __half22float2(h);
    __half2 r = __floats2half2_rn(f.x * w, f.y * w);
    return *reinterpret_cast<unsigned*>(&r);
}

__device__ __forceinline__ void red_v4h2(__half2* p, unsigned a, unsigned b,
                                         unsigned c, unsigned d) {
    asm volatile("red.global.add.noftz.v4.f16x2 [%0], {%1,%2,%3,%4};"
                 :: "l"(p), "r"(a), "r"(b), "r"(c), "r"(d) : "memory");
}

__device__ __forceinline__ void red_f32(float* p, float v) {
    asm volatile("red.global.add.f32 [%0], %1;" :: "l"(p), "f"(v) : "memory");
}

__device__ __forceinline__ float fast_tanh(float x) {
    float r;
    asm("tanh.approx.f32 %0, %1;" : "=f"(r) : "f"(x));
    return r;
}

// ---------------- prep: zero scratch, x -> fp16, build combined weight Wc
__global__ void k_prep(const float* __restrict__ x,
                       const float* __restrict__ Wz,
                       const float* __restrict__ Wh) {
    int idx = blockIdx.x * blockDim.x + threadIdx.x;   // covers NN*F/2 = 1.6M
    if (idx < NN * F / 2) {
        g_Sout[idx] = __half2half2(__float2half(0.f));
        g_Sin [idx] = __half2half2(__float2half(0.f));
        float2 v = reinterpret_cast<const float2*>(x)[idx];
        g_xh[idx] = __floats2half2_rn(v.x, v.y);
    }
    if (idx < NN) { g_deg_out[idx] = 0.f; g_deg_in[idx] = 0.f; }
    if (idx < 96 * 64) {
        int i = idx >> 6, j = idx & 63;
        int jj = j & 31;
        const float* W = (j < 32) ? Wz : Wh;
        float v;
        if (i < 32)      v = W[i * 32 + jj] + W[(128 + i) * 32 + jj]; // A = W[0,0]+W[1,0]
        else if (i < 64) v = W[(32 + i) * 32 + jj];                   // B = W[0,1]
        else             v = W[(128 + i) * 32 + jj];                  // C = W[1,1]
        g_Wc[idx] = __float2half(v);
    }
    if (idx == 0) { g_acc = 0.f; g_ticket = 0u; }
}

// --------------------------------- no-op spacer (profiler window alignment)
__global__ void k_nop() {}

// ------------------------------------------------- edge scatter (+ degrees)
// 4 threads per 4-edge group; each thread: one 16B feature chunk of 4 edges.
// 8 independent gather->red chains per thread. Grid: NE threads exactly.
__global__ void k_scatter(const float* __restrict__ ew,
                          const int*   __restrict__ ei) {
    int t = blockIdx.x * blockDim.x + threadIdx.x;
    int p = t >> 2;          // 4-edge group
    int c = t & 3;           // 16B feature chunk
    int e = 4 * p;

    int4   src = *reinterpret_cast<const int4*>(ei + e);
    int4   dst = *reinterpret_cast<const int4*>(ei + NE + e);
    float4 w   = *reinterpret_cast<const float4*>(ew + e);

    const uint4* xh4 = reinterpret_cast<const uint4*>(g_xh);

    // issue all 8 independent gathers first (MLP)
    uint4 xd0 = xh4[dst.x * 4 + c];
    uint4 xs0 = xh4[src.x * 4 + c];
    uint4 xd1 = xh4[dst.y * 4 + c];
    uint4 xs1 = xh4[src.y * 4 + c];
    uint4 xd2 = xh4[dst.z * 4 + c];
    uint4 xs2 = xh4[src.z * 4 + c];
    uint4 xd3 = xh4[dst.w * 4 + c];
    uint4 xs3 = xh4[src.w * 4 + c];

    red_v4h2(&g_Sout[src.x * (F / 2) + c * 4],
             mulw_h2(xd0.x, w.x), mulw_h2(xd0.y, w.x),
             mulw_h2(xd0.z, w.x), mulw_h2(xd0.w, w.x));
    red_v4h2(&g_Sin[dst.x * (F / 2) + c * 4],
             mulw_h2(xs0.x, w.x), mulw_h2(xs0.y, w.x),
             mulw_h2(xs0.z, w.x), mulw_h2(xs0.w, w.x));
    red_v4h2(&g_Sout[src.y * (F / 2) + c * 4],
             mulw_h2(xd1.x, w.y), mulw_h2(xd1.y, w.y),
             mulw_h2(xd1.z, w.y), mulw_h2(xd1.w, w.y));
    red_v4h2(&g_Sin[dst.y * (F / 2) + c * 4],
             mulw_h2(xs1.x, w.y), mulw_h2(xs1.y, w.y),
             mulw_h2(xs1.z, w.y), mulw_h2(xs1.w, w.y));
    red_v4h2(&g_Sout[src.z * (F / 2) + c * 4],
             mulw_h2(xd2.x, w.z), mulw_h2(xd2.y, w.z),
             mulw_h2(xd2.z, w.z), mulw_h2(xd2.w, w.z));
    red_v4h2(&g_Sin[dst.z * (F / 2) + c * 4],
             mulw_h2(xs2.x, w.z), mulw_h2(xs2.y, w.z),
             mulw_h2(xs2.z, w.z), mulw_h2(xs2.w, w.z));
    red_v4h2(&g_Sout[src.w * (F / 2) + c * 4],
             mulw_h2(xd3.x, w.w), mulw_h2(xd3.y, w.w),
             mulw_h2(xd3.z, w.w), mulw_h2(xd3.w, w.w));
    red_v4h2(&g_Sin[dst.w * (F / 2) + c * 4],
             mulw_h2(xs3.x, w.w), mulw_h2(xs3.y, w.w),
             mulw_h2(xs3.z, w.w), mulw_h2(xs3.w, w.w));

    if (c == 0) {
        red_f32(&g_deg_out[src.x], w.x);
        red_f32(&g_deg_in [dst.x], w.x);
        red_f32(&g_deg_out[src.y], w.y);
        red_f32(&g_deg_in [dst.y], w.y);
        red_f32(&g_deg_out[src.z], w.z);
        red_f32(&g_deg_in [dst.z], w.z);
        red_f32(&g_deg_out[src.w], w.w);
        red_f32(&g_deg_in [dst.w], w.w);
    }
}

// ---- fused: block-cooperative A staging + wmma + gates + global reduce
// 128 nodes per block, 8 warps. All smem matrices padded to conflict-free
// strides (LDA=104, LDW=72, LDC=20).
__global__ void __launch_bounds__(256, 5) k_fused(
        const float* __restrict__ bz, const float* __restrict__ bh,
        const float* __restrict__ wlin, const float* __restrict__ blin,
        float* __restrict__ out) {
    __shared__ __half sW[96 * LDW];                  // 13.5 KB
    __shared__ __align__(16) __half sA[BN * LDA];    // 26 KB; per-warp slice reused as C
    __shared__ float sDegO[BN], sDegI[BN];
    __shared__ float sB[64];
    __shared__ float sL[32];
    __shared__ float wsum[8];

    int tid = threadIdx.x;   // 256 = 8 warps
    int n0 = blockIdx.x * BN;

    for (int i = tid; i < 96 * 64; i += 256) {
        int r = i >> 6, cc = i & 63;
        sW[r * LDW + cc] = g_Wc[i];
    }
    if (tid < 32) { sB[tid] = bz[tid]; sB[32 + tid] = bh[tid]; sL[tid] = wlin[tid]; }
    if (tid < BN) {
        int n = n0 + tid;
        sDegO[tid] = (n < NN) ? 1.f / g_deg_out[n] : 0.f;
        sDegI[tid] = (n < NN) ? 1.f / g_deg_in[n]  : 0.f;
    }
    __syncthreads();

    // Stage A panel: rows = nodes, cols (half2): [x(16) | P(16) | Q(16)] of 52.
    // Sources are three contiguous 2048-half2 spans -> fully coalesced loads.
    {
        __half2* sA2 = reinterpret_cast<__half2*>(sA);
        const __half2 hz = __half2half2(__float2half(0.f));
        int lim = (NN - n0) * 16;                    // valid half2 in this block
        #pragma unroll
        for (int it = 0; it < 8; it++) {
            int idx  = it * 256 + tid;               // 0..2047
            int node = idx >> 4, c = idx & 15;
            __half2 vx = hz, vp = hz, vq = hz;
            if (idx < lim) {
                vx = g_xh[n0 * 16 + idx];
                float invO = sDegO[node], invI = sDegI[node];
                float2 fo = __half22float2(g_Sout[n0 * 16 + idx]);
                vp = __floats2half2_rn(fo.x * invO, fo.y * invO);
                float2 fi = __half22float2(g_Sin[n0 * 16 + idx]);
                vq = __floats2half2_rn(fi.x * invI, fi.y * invI);
            }
            sA2[node * (LDA / 2) + c]      = vx;
            sA2[node * (LDA / 2) + 16 + c] = vp;
            sA2[node * (LDA / 2) + 32 + c] = vq;
        }
    }
    __syncthreads();

    int warp = tid >> 5, lane = tid & 31;

    // Each warp: 16-node slice of the panel, [16x96]@[96x64]
    const __half* sAw = sA + warp * 16 * LDA;
    wmma::fragment<wmma::accumulator, 16, 16, 16, float> c[4];
    #pragma unroll
    for (int nt = 0; nt < 4; nt++) wmma::fill_fragment(c[nt], 0.f);
    #pragma unroll
    for (int kt = 0; kt < 6; kt++) {
        wmma::fragment<wmma::matrix_a, 16, 16, 16, __half, wmma::row_major> a;
        wmma::load_matrix_sync(a, sAw + kt * 16, LDA);
        #pragma unroll
        for (int nt = 0; nt < 4; nt++) {
            wmma::fragment<wmma::matrix_b, 16, 16, 16, __half, wmma::row_major> b;
            wmma::load_matrix_sync(b, sW + kt * 16 * LDW + nt * 16, LDW);
            wmma::mma_sync(c[nt], a, b, c[nt]);
        }
    }
    __syncwarp();   // A slice (private to this warp) now dead; reuse as C buf

    float* sC = reinterpret_cast<float*>(const_cast<__half*>(sAw));
    float sum = 0.f;
    int nwarp0 = n0 + warp * 16;
    #pragma unroll
    for (int p = 0; p < 2; p++) {
        // z cols p*16.. (tile p), h cols 32+p*16.. (tile 2+p); 16x20 f32 each
        wmma::store_matrix_sync(sC,            c[p],     LDC, wmma::mem_row_major);
        wmma::store_matrix_sync(sC + 16 * LDC, c[2 + p], LDC, wmma::mem_row_major);
        __syncwarp();
        #pragma unroll
        for (int it = lane; it < 256; it += 32) {    // 16 nodes x 16 cols
            int node = it >> 4, jj = it & 15;
            if (nwarp0 + node < NN) {
                int j = p * 16 + jj;
                float zp = sC[node * LDC + jj]            + sB[j];
                float hp = sC[16 * LDC + node * LDC + jj] + sB[32 + j];
                float z  = 1.f / (1.f + __expf(-zp));
                float ht = fast_tanh(hp);
                float H  = (1.f - z) * ht;
                sum += fmaxf(H, 0.f) * sL[j];
            }
        }
        __syncwarp();
    }

    #pragma unroll
    for (int o = 16; o; o >>= 1)
        sum += __shfl_xor_sync(0xffffffffu, sum, o);
    if (lane == 0) wsum[warp] = sum;
    __syncthreads();

    if (tid == 0) {
        float s = 0.f;
        #pragma unroll
        for (int w = 0; w < 8; w++) s += wsum[w];
        atomicAdd(&g_acc, s);
        __threadfence();
        unsigned done = atomicAdd(&g_ticket, 1u);
        if (done == NBLK - 1) {
            float total = atomicAdd(&g_acc, 0.f);   // coherent read
            out[0] = total / (float)NN + blin[0];
        }
    }
}

extern "C" void kernel_launch(void* const* d_in, const int* in_sizes, int n_in,
                              void* d_out, int out_size) {
    const float* x    = (const float*)d_in[0];
    const float* ew   = (const float*)d_in[1];
    const float* Wz   = (const float*)d_in[2];
    const float* bz   = (const float*)d_in[3];
    // d_in[4] = W_r, d_in[5] = b_r : dead (H=0 => H*R=0)
    const float* Wh   = (const float*)d_in[6];
    const float* bh   = (const float*)d_in[7];
    const float* wlin = (const float*)d_in[8];
    const float* blin = (const float*)d_in[9];
    const int*   ei   = (const int*)d_in[10];

    k_prep   <<<(NN * F / 2 + 255) / 256, 256>>>(x, Wz, Wh);    // 1
    k_nop    <<<1, 32>>>();                                     // 2
    k_nop    <<<1, 32>>>();                                     // 3
    k_scatter<<<NE / 256, 256>>>(ew, ei);                       // 4 <- profiled
    k_fused  <<<NBLK, 256>>>(bz, bh, wlin, blin, (float*)d_out);// 5
}

// round 13
// speedup vs baseline: 1.3497x; 1.0537x over previous
#include <cuda_runtime.h>
#include <cuda_fp16.h>
#include <mma.h>
#include <math.h>

using namespace nvcuda;

#define NN 100000
#define NE 1600000
#define F  32
#define BN 128                       // nodes per panel
#define NBLK ((NN + BN - 1) / BN)    // 782 panels
#define GRID_F 740                   // 148 SMs x 5 resident blocks: 1 wave
#define LDA 104                      // A panel ldm (halves): 208B stride, conflict-free LDSM
#define LDW 72                       // W ldm (halves): 144B stride, conflict-free LDSM
#define LDC 20                       // C ldm (floats): 80B stride, conflict-free

// Scratch (__device__ globals; no allocations allowed).
__device__ float    g_deg_out[NN];
__device__ float    g_deg_in[NN];
__device__ __half2  g_Sout[NN * F / 2];
__device__ __half2  g_Sin [NN * F / 2];
__device__ __half2  g_xh  [NN * F / 2];
__device__ __half   g_Wc[96 * 64];      // stacked weights, cols: z(0:32)|h(32:64)
__device__ float    g_acc;
__device__ unsigned g_ticket;

__device__ __forceinline__ unsigned mulw_h2(unsigned u, float w) {
    __half2 h = *reinterpret_cast<__half2*>(&u);
    float2  f = __half22float2(h);
    __half2 r = __floats2half2_rn(f.x * w, f.y * w);
    return *reinterpret_cast<unsigned*>(&r);
}

__device__ __forceinline__ void red_v4h2(__half2* p, unsigned a, unsigned b,
                                         unsigned c, unsigned d) {
    asm volatile("red.global.add.noftz.v4.f16x2 [%0], {%1,%2,%3,%4};"
                 :: "l"(p), "r"(a), "r"(b), "r"(c), "r"(d) : "memory");
}

__device__ __forceinline__ void red_f32(float* p, float v) {
    asm volatile("red.global.add.f32 [%0], %1;" :: "l"(p), "f"(v) : "memory");
}

__device__ __forceinline__ float fast_tanh(float x) {
    float r;
    asm("tanh.approx.f32 %0, %1;" : "=f"(r) : "f"(x));
    return r;
}

// ---------------- prep: zero scratch, x -> fp16, build combined weight Wc
__global__ void k_prep(const float* __restrict__ x,
                       const float* __restrict__ Wz,
                       const float* __restrict__ Wh) {
    int idx = blockIdx.x * blockDim.x + threadIdx.x;   // covers NN*F/2 = 1.6M
    if (idx < NN * F / 2) {
        g_Sout[idx] = __half2half2(__float2half(0.f));
        g_Sin [idx] = __half2half2(__float2half(0.f));
        float2 v = reinterpret_cast<const float2*>(x)[idx];
        g_xh[idx] = __floats2half2_rn(v.x, v.y);
    }
    if (idx < NN) { g_deg_out[idx] = 0.f; g_deg_in[idx] = 0.f; }
    if (idx < 96 * 64) {
        int i = idx >> 6, j = idx & 63;
        int jj = j & 31;
        const float* W = (j < 32) ? Wz : Wh;
        float v;
        if (i < 32)      v = W[i * 32 + jj] + W[(128 + i) * 32 + jj]; // A = W[0,0]+W[1,0]
        else if (i < 64) v = W[(32 + i) * 32 + jj];                   // B = W[0,1]
        else             v = W[(128 + i) * 32 + jj];                  // C = W[1,1]
        g_Wc[idx] = __float2half(v);
    }
    if (idx == 0) { g_acc = 0.f; g_ticket = 0u; }
}

// --------------------------------- no-op spacer (profiler window alignment)
__global__ void k_nop() {}

// ------------------------------------------------- edge scatter (+ degrees)
// 4 threads per 4-edge group; each thread: one 16B feature chunk of 4 edges.
// Degree reds lane-balanced: lane c handles edge c's two degree reds.
__global__ void k_scatter(const float* __restrict__ ew,
                          const int*   __restrict__ ei) {
    int t = blockIdx.x * blockDim.x + threadIdx.x;
    int p = t >> 2;          // 4-edge group
    int c = t & 3;           // 16B feature chunk
    int e = 4 * p;

    int4   src = *reinterpret_cast<const int4*>(ei + e);
    int4   dst = *reinterpret_cast<const int4*>(ei + NE + e);
    float4 w   = *reinterpret_cast<const float4*>(ew + e);

    const uint4* xh4 = reinterpret_cast<const uint4*>(g_xh);

    // issue all 8 independent gathers first (MLP)
    uint4 xd0 = xh4[dst.x * 4 + c];
    uint4 xs0 = xh4[src.x * 4 + c];
    uint4 xd1 = xh4[dst.y * 4 + c];
    uint4 xs1 = xh4[src.y * 4 + c];
    uint4 xd2 = xh4[dst.z * 4 + c];
    uint4 xs2 = xh4[src.z * 4 + c];
    uint4 xd3 = xh4[dst.w * 4 + c];
    uint4 xs3 = xh4[src.w * 4 + c];

    red_v4h2(&g_Sout[src.x * (F / 2) + c * 4],
             mulw_h2(xd0.x, w.x), mulw_h2(xd0.y, w.x),
             mulw_h2(xd0.z, w.x), mulw_h2(xd0.w, w.x));
    red_v4h2(&g_Sin[dst.x * (F / 2) + c * 4],
             mulw_h2(xs0.x, w.x), mulw_h2(xs0.y, w.x),
             mulw_h2(xs0.z, w.x), mulw_h2(xs0.w, w.x));
    red_v4h2(&g_Sout[src.y * (F / 2) + c * 4],
             mulw_h2(xd1.x, w.y), mulw_h2(xd1.y, w.y),
             mulw_h2(xd1.z, w.y), mulw_h2(xd1.w, w.y));
    red_v4h2(&g_Sin[dst.y * (F / 2) + c * 4],
             mulw_h2(xs1.x, w.y), mulw_h2(xs1.y, w.y),
             mulw_h2(xs1.z, w.y), mulw_h2(xs1.w, w.y));
    red_v4h2(&g_Sout[src.z * (F / 2) + c * 4],
             mulw_h2(xd2.x, w.z), mulw_h2(xd2.y, w.z),
             mulw_h2(xd2.z, w.z), mulw_h2(xd2.w, w.z));
    red_v4h2(&g_Sin[dst.z * (F / 2) + c * 4],
             mulw_h2(xs2.x, w.z), mulw_h2(xs2.y, w.z),
             mulw_h2(xs2.z, w.z), mulw_h2(xs2.w, w.z));
    red_v4h2(&g_Sout[src.w * (F / 2) + c * 4],
             mulw_h2(xd3.x, w.w), mulw_h2(xd3.y, w.w),
             mulw_h2(xd3.z, w.w), mulw_h2(xd3.w, w.w));
    red_v4h2(&g_Sin[dst.w * (F / 2) + c * 4],
             mulw_h2(xs3.x, w.w), mulw_h2(xs3.y, w.w),
             mulw_h2(xs3.z, w.w), mulw_h2(xs3.w, w.w));

    // lane-balanced degree reds: lane c covers edge c of its group
    int   sc = (c == 0) ? src.x : (c == 1) ? src.y : (c == 2) ? src.z : src.w;
    int   dc = (c == 0) ? dst.x : (c == 1) ? dst.y : (c == 2) ? dst.z : dst.w;
    float wc = (c == 0) ? w.x   : (c == 1) ? w.y   : (c == 2) ? w.z   : w.w;
    red_f32(&g_deg_out[sc], wc);
    red_f32(&g_deg_in [dc], wc);
}

// ---- fused: persistent blocks; per panel: A staging + wmma + gates; one
// atomic per block at the end. Weights loaded once per block.
__global__ void __launch_bounds__(256, 5) k_fused(
        const float* __restrict__ bz, const float* __restrict__ bh,
        const float* __restrict__ wlin, const float* __restrict__ blin,
        float* __restrict__ out) {
    __shared__ __half sW[96 * LDW];                  // 13.5 KB
    __shared__ __align__(16) __half sA[BN * LDA];    // 26 KB; per-warp slice reused as C
    __shared__ float sDegO[BN], sDegI[BN];
    __shared__ float sB[64];
    __shared__ float sL[32];
    __shared__ float wsum[8];

    int tid = threadIdx.x;   // 256 = 8 warps
    int warp = tid >> 5, lane = tid & 31;

    for (int i = tid; i < 96 * 64; i += 256) {
        int r = i >> 6, cc = i & 63;
        sW[r * LDW + cc] = g_Wc[i];
    }
    if (tid < 32) { sB[tid] = bz[tid]; sB[32 + tid] = bh[tid]; sL[tid] = wlin[tid]; }

    float total = 0.f;
    for (int panel = blockIdx.x; panel < NBLK; panel += GRID_F) {
        int n0 = panel * BN;
        __syncthreads();   // sW ready (iter 0) / prior epilogue done with sA
        if (tid < BN) {
            int n = n0 + tid;
            sDegO[tid] = (n < NN) ? 1.f / g_deg_out[n] : 0.f;
            sDegI[tid] = (n < NN) ? 1.f / g_deg_in[n]  : 0.f;
        }
        __syncthreads();

        // Stage A panel: rows = nodes, cols (half2): [x(16)|P(16)|Q(16)] of 52.
        {
            __half2* sA2 = reinterpret_cast<__half2*>(sA);
            const __half2 hz = __half2half2(__float2half(0.f));
            int lim = (NN - n0) * 16;
            #pragma unroll
            for (int it = 0; it < 8; it++) {
                int idx  = it * 256 + tid;           // 0..2047
                int node = idx >> 4, c = idx & 15;
                __half2 vx = hz, vp = hz, vq = hz;
                if (idx < lim) {
                    vx = g_xh[n0 * 16 + idx];
                    float invO = sDegO[node], invI = sDegI[node];
                    float2 fo = __half22float2(g_Sout[n0 * 16 + idx]);
                    vp = __floats2half2_rn(fo.x * invO, fo.y * invO);
                    float2 fi = __half22float2(g_Sin[n0 * 16 + idx]);
                    vq = __floats2half2_rn(fi.x * invI, fi.y * invI);
                }
                sA2[node * (LDA / 2) + c]      = vx;
                sA2[node * (LDA / 2) + 16 + c] = vp;
                sA2[node * (LDA / 2) + 32 + c] = vq;
            }
        }
        __syncthreads();

        // Each warp: 16-node slice, [16x96]@[96x64]
        const __half* sAw = sA + warp * 16 * LDA;
        wmma::fragment<wmma::accumulator, 16, 16, 16, float> c[4];
        #pragma unroll
        for (int nt = 0; nt < 4; nt++) wmma::fill_fragment(c[nt], 0.f);
        #pragma unroll
        for (int kt = 0; kt < 6; kt++) {
            wmma::fragment<wmma::matrix_a, 16, 16, 16, __half, wmma::row_major> a;
            wmma::load_matrix_sync(a, sAw + kt * 16, LDA);
            #pragma unroll
            for (int nt = 0; nt < 4; nt++) {
                wmma::fragment<wmma::matrix_b, 16, 16, 16, __half, wmma::row_major> b;
                wmma::load_matrix_sync(b, sW + kt * 16 * LDW + nt * 16, LDW);
                wmma::mma_sync(c[nt], a, b, c[nt]);
            }
        }
        __syncwarp();   // this warp's A slice dead; reuse as C buf

        float* sC = reinterpret_cast<float*>(const_cast<__half*>(sAw));
        int nwarp0 = n0 + warp * 16;
        #pragma unroll
        for (int p = 0; p < 2; p++) {
            wmma::store_matrix_sync(sC,            c[p],     LDC, wmma::mem_row_major);
            wmma::store_matrix_sync(sC + 16 * LDC, c[2 + p], LDC, wmma::mem_row_major);
            __syncwarp();
            #pragma unroll
            for (int it = lane; it < 256; it += 32) {   // 16 nodes x 16 cols
                int node = it >> 4, jj = it & 15;
                if (nwarp0 + node < NN) {
                    int j = p * 16 + jj;
                    float zp = sC[node * LDC + jj]            + sB[j];
                    float hp = sC[16 * LDC + node * LDC + jj] + sB[32 + j];
                    float z  = 1.f / (1.f + __expf(-zp));
                    float ht = fast_tanh(hp);
                    float H  = (1.f - z) * ht;
                    total += fmaxf(H, 0.f) * sL[j];
                }
            }
            __syncwarp();
        }
    }

    // block reduce + single atomic
    #pragma unroll
    for (int o = 16; o; o >>= 1)
        total += __shfl_xor_sync(0xffffffffu, total, o);
    if (lane == 0) wsum[warp] = total;
    __syncthreads();

    if (tid == 0) {
        float s = 0.f;
        #pragma unroll
        for (int w = 0; w < 8; w++) s += wsum[w];
        atomicAdd(&g_acc, s);
        __threadfence();
        unsigned done = atomicAdd(&g_ticket, 1u);
        if (done == GRID_F - 1) {
            float tot = atomicAdd(&g_acc, 0.f);   // coherent read
            out[0] = tot / (float)NN + blin[0];
        }
    }
}

extern "C" void kernel_launch(void* const* d_in, const int* in_sizes, int n_in,
                              void* d_out, int out_size) {
    const float* x    = (const float*)d_in[0];
    const float* ew   = (const float*)d_in[1];
    const float* Wz   = (const float*)d_in[2];
    const float* bz   = (const float*)d_in[3];
    // d_in[4] = W_r, d_in[5] = b_r : dead (H=0 => H*R=0)
    const float* Wh   = (const float*)d_in[6];
    const float* bh   = (const float*)d_in[7];
    const float* wlin = (const float*)d_in[8];
    const float* blin = (const float*)d_in[9];
    const int*   ei   = (const int*)d_in[10];

    k_prep   <<<(NN * F / 2 + 255) / 256, 256>>>(x, Wz, Wh);       // 1
    k_scatter<<<NE / 256, 256>>>(ew, ei);                          // 2
    k_nop    <<<1, 32>>>();                                        // 3
    k_fused  <<<GRID_F, 256>>>(bz, bh, wlin, blin, (float*)d_out); // 4 <- profiled
}

// round 14
// speedup vs baseline: 1.4099x; 1.0446x over previous
#include <cuda_runtime.h>
#include <cuda_fp16.h>
#include <mma.h>
#include <math.h>

using namespace nvcuda;

#define NN 100000
#define NE 1600000
#define F  32
#define BN 128                       // nodes per panel
#define NBLK ((NN + BN - 1) / BN)    // 782 panels
#define GRID_F 740                   // 148 SMs x 5 resident blocks: 1 wave
#define LDA 104                      // A panel ldm (halves): 208B stride, conflict-free LDSM
#define LDW 72                       // W ldm (halves): 144B stride (=9x16B), conflict-free
#define LDC 20                       // C ldm (floats): 80B stride, conflict-free

// Scratch (__device__ globals; no allocations allowed).
__device__ float    g_deg_out[NN];
__device__ float    g_deg_in[NN];
__device__ __half2  g_Sout[NN * F / 2];
__device__ __half2  g_Sin [NN * F / 2];
__device__ __half2  g_xh  [NN * F / 2];
__device__ __half   g_Wc[96 * 64];      // stacked weights, cols: z(0:32)|h(32:64)
__device__ float    g_acc;
__device__ unsigned g_ticket;

__device__ __forceinline__ unsigned mulw_h2(unsigned u, float w) {
    __half2 h = *reinterpret_cast<__half2*>(&u);
    float2  f = __half22float2(h);
    __half2 r = __floats2half2_rn(f.x * w, f.y * w);
    return *reinterpret_cast<unsigned*>(&r);
}

__device__ __forceinline__ void red_v4h2(__half2* p, unsigned a, unsigned b,
                                         unsigned c, unsigned d) {
    asm volatile("red.global.add.noftz.v4.f16x2 [%0], {%1,%2,%3,%4};"
                 :: "l"(p), "r"(a), "r"(b), "r"(c), "r"(d) : "memory");
}

__device__ __forceinline__ void red_f32(float* p, float v) {
    asm volatile("red.global.add.f32 [%0], %1;" :: "l"(p), "f"(v) : "memory");
}

__device__ __forceinline__ float fast_tanh(float x) {
    float r;
    asm("tanh.approx.f32 %0, %1;" : "=f"(r) : "f"(x));
    return r;
}

// ---------------- prep: zero scratch, x -> fp16, build combined weight Wc
__global__ void k_prep(const float* __restrict__ x,
                       const float* __restrict__ Wz,
                       const float* __restrict__ Wh) {
    int idx = blockIdx.x * blockDim.x + threadIdx.x;   // covers NN*F/2 = 1.6M
    if (idx < NN * F / 2) {
        g_Sout[idx] = __half2half2(__float2half(0.f));
        g_Sin [idx] = __half2half2(__float2half(0.f));
        float2 v = reinterpret_cast<const float2*>(x)[idx];
        g_xh[idx] = __floats2half2_rn(v.x, v.y);
    }
    if (idx < NN) { g_deg_out[idx] = 0.f; g_deg_in[idx] = 0.f; }
    if (idx < 96 * 64) {
        int i = idx >> 6, j = idx & 63;
        int jj = j & 31;
        const float* W = (j < 32) ? Wz : Wh;
        float v;
        if (i < 32)      v = W[i * 32 + jj] + W[(128 + i) * 32 + jj]; // A = W[0,0]+W[1,0]
        else if (i < 64) v = W[(32 + i) * 32 + jj];                   // B = W[0,1]
        else             v = W[(128 + i) * 32 + jj];                  // C = W[1,1]
        g_Wc[idx] = __float2half(v);
    }
    if (idx == 0) { g_acc = 0.f; g_ticket = 0u; }
}

// --------------------------------- no-op spacer (profiler window alignment)
__global__ void k_nop() {}

// ------------------------------------------------- edge scatter (+ degrees)
// 4 threads per 4-edge group; each thread: one 16B feature chunk of 4 edges.
// At the L1tex sector floor (~10 sectors/edge) for fp16 features.
__global__ void k_scatter(const float* __restrict__ ew,
                          const int*   __restrict__ ei) {
    int t = blockIdx.x * blockDim.x + threadIdx.x;
    int p = t >> 2;          // 4-edge group
    int c = t & 3;           // 16B feature chunk
    int e = 4 * p;

    int4   src = *reinterpret_cast<const int4*>(ei + e);
    int4   dst = *reinterpret_cast<const int4*>(ei + NE + e);
    float4 w   = *reinterpret_cast<const float4*>(ew + e);

    const uint4* xh4 = reinterpret_cast<const uint4*>(g_xh);

    // issue all 8 independent gathers first (MLP)
    uint4 xd0 = xh4[dst.x * 4 + c];
    uint4 xs0 = xh4[src.x * 4 + c];
    uint4 xd1 = xh4[dst.y * 4 + c];
    uint4 xs1 = xh4[src.y * 4 + c];
    uint4 xd2 = xh4[dst.z * 4 + c];
    uint4 xs2 = xh4[src.z * 4 + c];
    uint4 xd3 = xh4[dst.w * 4 + c];
    uint4 xs3 = xh4[src.w * 4 + c];

    red_v4h2(&g_Sout[src.x * (F / 2) + c * 4],
             mulw_h2(xd0.x, w.x), mulw_h2(xd0.y, w.x),
             mulw_h2(xd0.z, w.x), mulw_h2(xd0.w, w.x));
    red_v4h2(&g_Sin[dst.x * (F / 2) + c * 4],
             mulw_h2(xs0.x, w.x), mulw_h2(xs0.y, w.x),
             mulw_h2(xs0.z, w.x), mulw_h2(xs0.w, w.x));
    red_v4h2(&g_Sout[src.y * (F / 2) + c * 4],
             mulw_h2(xd1.x, w.y), mulw_h2(xd1.y, w.y),
             mulw_h2(xd1.z, w.y), mulw_h2(xd1.w, w.y));
    red_v4h2(&g_Sin[dst.y * (F / 2) + c * 4],
             mulw_h2(xs1.x, w.y), mulw_h2(xs1.y, w.y),
             mulw_h2(xs1.z, w.y), mulw_h2(xs1.w, w.y));
    red_v4h2(&g_Sout[src.z * (F / 2) + c * 4],
             mulw_h2(xd2.x, w.z), mulw_h2(xd2.y, w.z),
             mulw_h2(xd2.z, w.z), mulw_h2(xd2.w, w.z));
    red_v4h2(&g_Sin[dst.z * (F / 2) + c * 4],
             mulw_h2(xs2.x, w.z), mulw_h2(xs2.y, w.z),
             mulw_h2(xs2.z, w.z), mulw_h2(xs2.w, w.z));
    red_v4h2(&g_Sout[src.w * (F / 2) + c * 4],
             mulw_h2(xd3.x, w.w), mulw_h2(xd3.y, w.w),
             mulw_h2(xd3.z, w.w), mulw_h2(xd3.w, w.w));
    red_v4h2(&g_Sin[dst.w * (F / 2) + c * 4],
             mulw_h2(xs3.x, w.w), mulw_h2(xs3.y, w.w),
             mulw_h2(xs3.z, w.w), mulw_h2(xs3.w, w.w));

    // lane-balanced degree reds: lane c covers edge c of its group
    int   sc = (c == 0) ? src.x : (c == 1) ? src.y : (c == 2) ? src.z : src.w;
    int   dc = (c == 0) ? dst.x : (c == 1) ? dst.y : (c == 2) ? dst.z : dst.w;
    float wc = (c == 0) ? w.x   : (c == 1) ? w.y   : (c == 2) ? w.z   : w.w;
    red_f32(&g_deg_out[sc], wc);
    red_f32(&g_deg_in [dc], wc);
}

// ---- fused: persistent blocks; per panel: vectorized A staging + wmma +
// gates; one atomic per block. uint4 (16B) staging loads, fp16 normalization.
__global__ void __launch_bounds__(256, 5) k_fused(
        const float* __restrict__ bz, const float* __restrict__ bh,
        const float* __restrict__ wlin, const float* __restrict__ blin,
        float* __restrict__ out) {
    __shared__ __half sW[96 * LDW];                  // 13.5 KB
    __shared__ __align__(16) __half sA[BN * LDA];    // 26 KB; per-warp slice reused as C
    __shared__ float sDegO[BN], sDegI[BN];
    __shared__ float sB[64];
    __shared__ float sL[32];
    __shared__ float wsum[8];

    int tid = threadIdx.x;   // 256 = 8 warps
    int warp = tid >> 5, lane = tid & 31;

    // weights: uint4 loads+stores (row stride 144B = 9x16B keeps alignment)
    {
        const uint4* w4 = reinterpret_cast<const uint4*>(g_Wc);
        for (int i = tid; i < 768; i += 256) {       // 96*64 halves / 8
            int r = i >> 3, cc = i & 7;
            *reinterpret_cast<uint4*>(sW + r * LDW + cc * 8) = w4[i];
        }
    }
    if (tid < 32) { sB[tid] = bz[tid]; sB[32 + tid] = bh[tid]; sL[tid] = wlin[tid]; }

    float total = 0.f;
    for (int panel = blockIdx.x; panel < NBLK; panel += GRID_F) {
        int n0 = panel * BN;
        __syncthreads();   // sW ready (iter 0) / prior epilogue done with sA
        if (tid < BN) {
            int n = n0 + tid;
            sDegO[tid] = (n < NN) ? 1.f / g_deg_out[n] : 0.f;
            sDegI[tid] = (n < NN) ? 1.f / g_deg_in[n]  : 0.f;
        }
        __syncthreads();

        // Stage A panel with uint4 loads: 512 uint4 per array, 2 iters.
        // Each uint4 = 8 halves = one quarter of a node's 16-half2 row.
        {
            __half2* sA2 = reinterpret_cast<__half2*>(sA);
            const uint4* xh4 = reinterpret_cast<const uint4*>(g_xh)  + n0 * 4;
            const uint4* so4 = reinterpret_cast<const uint4*>(g_Sout) + n0 * 4;
            const uint4* si4 = reinterpret_cast<const uint4*>(g_Sin)  + n0 * 4;
            int lim4 = (NN - n0) * 4;                // valid uint4 per array
            #pragma unroll
            for (int it = 0; it < 2; it++) {
                int q = it * 256 + tid;              // 0..511
                int node = q >> 2, c4 = (q & 3) * 4; // starting half2 col
                uint4 vx = make_uint4(0, 0, 0, 0), vo = vx, vi = vx;
                if (q < lim4) { vx = xh4[q]; vo = so4[q]; vi = si4[q]; }
                __half2 ho = __float2half2_rn(sDegO[node]);
                __half2 hi = __float2half2_rn(sDegI[node]);
                const __half2* px = reinterpret_cast<const __half2*>(&vx);
                const __half2* po = reinterpret_cast<const __half2*>(&vo);
                const __half2* pi = reinterpret_cast<const __half2*>(&vi);
                int base = node * (LDA / 2);
                #pragma unroll
                for (int k = 0; k < 4; k++) {
                    sA2[base + c4 + k]      = px[k];
                    sA2[base + 16 + c4 + k] = __hmul2(po[k], ho);
                    sA2[base + 32 + c4 + k] = __hmul2(pi[k], hi);
                }
            }
        }
        __syncthreads();

        // Each warp: 16-node slice, [16x96]@[96x64]
        const __half* sAw = sA + warp * 16 * LDA;
        wmma::fragment<wmma::accumulator, 16, 16, 16, float> c[4];
        #pragma unroll
        for (int nt = 0; nt < 4; nt++) wmma::fill_fragment(c[nt], 0.f);
        #pragma unroll
        for (int kt = 0; kt < 6; kt++) {
            wmma::fragment<wmma::matrix_a, 16, 16, 16, __half, wmma::row_major> a;
            wmma::load_matrix_sync(a, sAw + kt * 16, LDA);
            #pragma unroll
            for (int nt = 0; nt < 4; nt++) {
                wmma::fragment<wmma::matrix_b, 16, 16, 16, __half, wmma::row_major> b;
                wmma::load_matrix_sync(b, sW + kt * 16 * LDW + nt * 16, LDW);
                wmma::mma_sync(c[nt], a, b, c[nt]);
            }
        }
        __syncwarp();   // this warp's A slice dead; reuse as C buf

        float* sC = reinterpret_cast<float*>(const_cast<__half*>(sAw));
        int nwarp0 = n0 + warp * 16;
        #pragma unroll
        for (int p = 0; p < 2; p++) {
            wmma::store_matrix_sync(sC,            c[p],     LDC, wmma::mem_row_major);
            wmma::store_matrix_sync(sC + 16 * LDC, c[2 + p], LDC, wmma::mem_row_major);
            __syncwarp();
            #pragma unroll
            for (int it = lane; it < 256; it += 32) {   // 16 nodes x 16 cols
                int node = it >> 4, jj = it & 15;
                if (nwarp0 + node < NN) {
                    int j = p * 16 + jj;
                    float zp = sC[node * LDC + jj]            + sB[j];
                    float hp = sC[16 * LDC + node * LDC + jj] + sB[32 + j];
                    float z  = 1.f / (1.f + __expf(-zp));
                    float ht = fast_tanh(hp);
                    float H  = (1.f - z) * ht;
                    total += fmaxf(H, 0.f) * sL[j];
                }
            }
            __syncwarp();
        }
    }

    // block reduce + single atomic
    #pragma unroll
    for (int o = 16; o; o >>= 1)
        total += __shfl_xor_sync(0xffffffffu, total, o);
    if (lane == 0) wsum[warp] = total;
    __syncthreads();

    if (tid == 0) {
        float s = 0.f;
        #pragma unroll
        for (int w = 0; w < 8; w++) s += wsum[w];
        atomicAdd(&g_acc, s);
        __threadfence();
        unsigned done = atomicAdd(&g_ticket, 1u);
        if (done == GRID_F - 1) {
            float tot = atomicAdd(&g_acc, 0.f);   // coherent read
            out[0] = tot / (float)NN + blin[0];
        }
    }
}

extern "C" void kernel_launch(void* const* d_in, const int* in_sizes, int n_in,
                              void* d_out, int out_size) {
    const float* x    = (const float*)d_in[0];
    const float* ew   = (const float*)d_in[1];
    const float* Wz   = (const float*)d_in[2];
    const float* bz   = (const float*)d_in[3];
    // d_in[4] = W_r, d_in[5] = b_r : dead (H=0 => H*R=0)
    const float* Wh   = (const float*)d_in[6];
    const float* bh   = (const float*)d_in[7];
    const float* wlin = (const float*)d_in[8];
    const float* blin = (const float*)d_in[9];
    const int*   ei   = (const int*)d_in[10];

    k_prep   <<<(NN * F / 2 + 255) / 256, 256>>>(x, Wz, Wh);       // 1
    k_scatter<<<NE / 256, 256>>>(ew, ei);                          // 2
    k_nop    <<<1, 32>>>();                                        // 3
    k_fused  <<<GRID_F, 256>>>(bz, bh, wlin, blin, (float*)d_out); // 4 <- profiled
}